// round 1
// baseline (speedup 1.0000x reference)
#include <cuda_runtime.h>

// Problem constants
#define T_DIM 1024
#define N_DIM 32
#define CI    512
#define CO    512

// Scratch (allocation-free rule: __device__ globals)
__device__ float g_z[T_DIM * N_DIM * CO];   // [t][n][o]  64 MB
__device__ float g_RT[CO * CO];             // RT[o][p] = R[p][o]

// ---------------------------------------------------------------------------
// Kernel 1: transpose R -> RT so the sparse gather reads coalesced rows.
// ---------------------------------------------------------------------------
__global__ void transpose_R_kernel(const float* __restrict__ R) {
    int idx = blockIdx.x * blockDim.x + threadIdx.x;   // idx = o*CO + p
    int o = idx >> 9;
    int p = idx & 511;
    g_RT[idx] = R[p * CO + o];
}

// ---------------------------------------------------------------------------
// Kernel 2: z[t][n][o] = sum_c x[n][c][t] * W[o][c]
// Tiled fp32 GEMM: BM=128 (t), BN=64 (o), BK=16 (c), 256 threads, 8x4 micro.
// ---------------------------------------------------------------------------
#define BM 128
#define BN 64
#define BK 16
#define WS_STRIDE 68   // pad to kill STS bank conflicts, keep 16B alignment

__global__ __launch_bounds__(256) void gemm_z_kernel(
    const float* __restrict__ x, const float* __restrict__ W)
{
    __shared__ float xs[BK][BM];          // [c][t]
    __shared__ float ws[BK][WS_STRIDE];   // [c][o] (padded)

    const int n  = blockIdx.z;
    const int t0 = blockIdx.x * BM;
    const int o0 = blockIdx.y * BN;
    const int tid = threadIdx.x;
    const int tx = tid & 15;    // o micro-col (4 outputs)
    const int ty = tid >> 4;    // t micro-row (8 outputs)

    float acc[8][4];
#pragma unroll
    for (int i = 0; i < 8; ++i)
#pragma unroll
        for (int j = 0; j < 4; ++j) acc[i][j] = 0.f;

    const float* xbase = x + (size_t)n * CI * T_DIM + t0;

    for (int c0 = 0; c0 < CI; c0 += BK) {
        // x tile: 16 x 128, coalesced along t
#pragma unroll
        for (int it = 0; it < 8; ++it) {
            int idx = tid + it * 256;
            int cc = idx >> 7;
            int tt = idx & 127;
            xs[cc][tt] = xbase[(c0 + cc) * T_DIM + tt];
        }
        // W tile: 64 x 16 -> stored transposed ws[c][o]
#pragma unroll
        for (int it = 0; it < 4; ++it) {
            int idx = tid + it * 256;
            int oo = idx >> 4;
            int cc = idx & 15;
            ws[cc][oo] = W[(o0 + oo) * CI + (c0 + cc)];
        }
        __syncthreads();

#pragma unroll
        for (int k = 0; k < BK; ++k) {
            float a[8], b[4];
#pragma unroll
            for (int i = 0; i < 8; ++i) a[i] = xs[k][ty * 8 + i];
#pragma unroll
            for (int j = 0; j < 4; ++j) b[j] = ws[k][tx * 4 + j];
#pragma unroll
            for (int i = 0; i < 8; ++i)
#pragma unroll
                for (int j = 0; j < 4; ++j)
                    acc[i][j] += a[i] * b[j];
        }
        __syncthreads();
    }

    // write z[t][n][o], vectorized float4 along o
#pragma unroll
    for (int i = 0; i < 8; ++i) {
        int t = t0 + ty * 8 + i;
        float4 v4 = make_float4(acc[i][0], acc[i][1], acc[i][2], acc[i][3]);
        *(float4*)&g_z[((size_t)t * N_DIM + n) * CO + o0 + tx * 4] = v4;
    }
}

// ---------------------------------------------------------------------------
// Kernel 3: sequential LIF scan with sparse recurrent gather.
// One CTA per batch n, one thread per output neuron p.
//   rec[p] = z[t][n][p] + sum_{o : s[o]=1} RT[o][p]
//   i = 0.75*i + rec ;  v = 0.9*v*(1-s) + i ;  s' = (v >= 1)
// Output delayed by one step; staged in smem in 16-step blocks for coalescing.
// ---------------------------------------------------------------------------
#define STAGE_T 16
#define STAGE_STRIDE (STAGE_T + 1)   // 17, kills bank conflicts on writes

__global__ __launch_bounds__(512) void scan_kernel(float* __restrict__ out) {
    const int n    = blockIdx.x;
    const int p    = threadIdx.x;
    const int warp = p >> 5;
    const int lane = p & 31;

    __shared__ int   s_cnt[16];
    __shared__ short s_list[512];
    __shared__ float stage[512 * STAGE_STRIDE];   // ~34.8 KB

    float cur = 0.f, v = 0.f, s = 0.f;

    // q = 0 output slot is zero (delay shift)
    stage[p * STAGE_STRIDE + 0] = 0.f;

    for (int t = 0; t < T_DIM - 1; ++t) {
        // ---- build compact spike index list for current s ----
        unsigned bal = __ballot_sync(0xffffffffu, s > 0.5f);
        if (lane == 0) s_cnt[warp] = __popc(bal);
        __syncthreads();

        int off = 0, total = 0;
#pragma unroll
        for (int w = 0; w < 16; ++w) {
            int c = s_cnt[w];
            if (w < warp) off += c;
            total += c;
        }
        if (s > 0.5f) {
            int r = off + __popc(bal & ((1u << lane) - 1u));
            s_list[r] = (short)p;
        }
        __syncthreads();

        // ---- gather: rec = z + sum over spiking columns of RT ----
        float zv = g_z[((size_t)t * N_DIM + n) * CO + p];
        float acc0 = 0.f, acc1 = 0.f, acc2 = 0.f, acc3 = 0.f;
        int j = 0;
        for (; j + 4 <= total; j += 4) {
            int o0 = s_list[j];
            int o1 = s_list[j + 1];
            int o2 = s_list[j + 2];
            int o3 = s_list[j + 3];
            acc0 += g_RT[o0 * CO + p];
            acc1 += g_RT[o1 * CO + p];
            acc2 += g_RT[o2 * CO + p];
            acc3 += g_RT[o3 * CO + p];
        }
        for (; j < total; ++j) acc0 += g_RT[s_list[j] * CO + p];
        float rec = zv + ((acc0 + acc1) + (acc2 + acc3));

        // ---- LIF state update ----
        cur = 0.75f * cur + rec;
        v   = 0.9f * v * (1.f - s) + cur;
        float s_new = (v >= 1.0f) ? 1.f : 0.f;
        s = s_new;

        // ---- stage output at q = t+1 ----
        int q = t + 1;
        stage[p * STAGE_STRIDE + (q & (STAGE_T - 1))] = s_new;

        if ((q & (STAGE_T - 1)) == STAGE_T - 1) {
            __syncthreads();
            int qbase = q & ~(STAGE_T - 1);
            // flush 512 x 16 values, coalesced along t
#pragma unroll
            for (int it = 0; it < STAGE_T; ++it) {
                int vidx = it * 512 + p;
                int pp = vidx >> 4;          // neuron
                int tt = vidx & (STAGE_T - 1);
                out[((size_t)n * CO + pp) * T_DIM + qbase + tt] =
                    stage[pp * STAGE_STRIDE + tt];
            }
        }
        __syncthreads();   // protects s_cnt / s_list / stage reuse
    }
}

// ---------------------------------------------------------------------------
// Launch
// ---------------------------------------------------------------------------
extern "C" void kernel_launch(void* const* d_in, const int* in_sizes, int n_in,
                              void* d_out, int out_size)
{
    const float* x = (const float*)d_in[0];   // [32, 512, 1024]
    const float* W = (const float*)d_in[1];   // [512, 512]
    const float* R = (const float*)d_in[2];   // [512, 512]
    float* out = (float*)d_out;               // [32, 512, 1024]

    // RT transpose: 512*512 elements
    transpose_R_kernel<<<(CO * CO) / 256, 256>>>(R);

    // z GEMM: grid (t-tiles, o-tiles, n)
    dim3 ggrid(T_DIM / BM, CO / BN, N_DIM);
    gemm_z_kernel<<<ggrid, 256>>>(x, W);

    // sequential scan: one CTA per batch
    scan_kernel<<<N_DIM, 512>>>(out);
}

// round 4
// speedup vs baseline: 1.2841x; 1.2841x over previous
#include <cuda_runtime.h>
#include <cstdint>

// Problem constants
#define T_DIM 1024
#define N_DIM 32
#define CI    512
#define CO    512

// Scratch (allocation-free rule: __device__ globals)
__device__ float g_z[T_DIM * N_DIM * CO];   // [t][n][o]
__device__ float g_RT[CO * CO];             // RT[o][p] = R[p][o]

// ---------------------------------------------------------------------------
// Kernel 1: transpose R -> RT (row o = contributions of spike o, coalesced).
// ---------------------------------------------------------------------------
__global__ void transpose_R_kernel(const float* __restrict__ R) {
    int idx = blockIdx.x * blockDim.x + threadIdx.x;   // idx = o*CO + p
    int o = idx >> 9;
    int p = idx & 511;
    g_RT[idx] = R[p * CO + o];
}

// ---------------------------------------------------------------------------
// Kernel 2: z[t][n][o] = sum_c x[n][c][t] * W[o][c]   (proven in R1)
// ---------------------------------------------------------------------------
#define BM 128
#define BN 64
#define BK 16
#define WS_STRIDE 68

__global__ __launch_bounds__(256) void gemm_z_kernel(
    const float* __restrict__ x, const float* __restrict__ W)
{
    __shared__ float xs[BK][BM];
    __shared__ float ws[BK][WS_STRIDE];

    const int n  = blockIdx.z;
    const int t0 = blockIdx.x * BM;
    const int o0 = blockIdx.y * BN;
    const int tid = threadIdx.x;
    const int tx = tid & 15;
    const int ty = tid >> 4;

    float acc[8][4];
#pragma unroll
    for (int i = 0; i < 8; ++i)
#pragma unroll
        for (int j = 0; j < 4; ++j) acc[i][j] = 0.f;

    const float* xbase = x + (size_t)n * CI * T_DIM + t0;

    for (int c0 = 0; c0 < CI; c0 += BK) {
#pragma unroll
        for (int it = 0; it < 8; ++it) {
            int idx = tid + it * 256;
            int cc = idx >> 7;
            int tt = idx & 127;
            xs[cc][tt] = xbase[(c0 + cc) * T_DIM + tt];
        }
#pragma unroll
        for (int it = 0; it < 4; ++it) {
            int idx = tid + it * 256;
            int oo = idx >> 4;
            int cc = idx & 15;
            ws[cc][oo] = W[(o0 + oo) * CI + (c0 + cc)];
        }
        __syncthreads();

#pragma unroll
        for (int k = 0; k < BK; ++k) {
            float a[8], b[4];
#pragma unroll
            for (int i = 0; i < 8; ++i) a[i] = xs[k][ty * 8 + i];
#pragma unroll
            for (int j = 0; j < 4; ++j) b[j] = ws[k][tx * 4 + j];
#pragma unroll
            for (int i = 0; i < 8; ++i)
#pragma unroll
                for (int j = 0; j < 4; ++j)
                    acc[i][j] += a[i] * b[j];
        }
        __syncthreads();
    }

#pragma unroll
    for (int i = 0; i < 8; ++i) {
        int t = t0 + ty * 8 + i;
        float4 v4 = make_float4(acc[i][0], acc[i][1], acc[i][2], acc[i][3]);
        *(float4*)&g_z[((size_t)t * N_DIM + n) * CO + o0 + tx * 4] = v4;
    }
}

// ---------------------------------------------------------------------------
// Kernel 3: sequential LIF scan, R1 structure (one CTA per batch, 512 thr),
// but with a vectorized, latency-pipelined gather:
//   - warps 0..3 (threads 0..127) gather: thread g handles columns 4g..4g+3
//     with float4 loads, chunked 8 rows at a time, double-buffered (MLP 8).
//   - Accumulation order per column is BIT-IDENTICAL to R1:
//     slot = list position mod 4 into acc0..acc3, groups of 4 while
//     j+4<=total, tail into acc0, rec = zv + ((a0+a1)+(a2+a3)).
//   - rec handed to owner threads via smem; LIF/ballot/staging verbatim R1.
// ---------------------------------------------------------------------------
#define STAGE_T 16
#define STAGE_STRIDE (STAGE_T + 1)

__global__ __launch_bounds__(512, 1) void scan_kernel(float* __restrict__ out) {
    const int n    = blockIdx.x;
    const int p    = threadIdx.x;
    const int warp = p >> 5;
    const int lane = p & 31;

    __shared__ int   s_cnt[16];
    __shared__ short s_list[512];
    __shared__ int   s_total;
    __shared__ float recbuf[512];
    __shared__ float stage[512 * STAGE_STRIDE];

    float cur = 0.f, v = 0.f, s = 0.f;

    // q = 0 output slot is zero (delay shift)
    stage[p * STAGE_STRIDE + 0] = 0.f;

    const float4* RT4 = (const float4*)g_RT;   // row stride CO/4 = 128 float4s

    for (int t = 0; t < T_DIM - 1; ++t) {
        // ---- build compact spike index list for current s (verbatim R1) ----
        unsigned bal = __ballot_sync(0xffffffffu, s > 0.5f);
        if (lane == 0) s_cnt[warp] = __popc(bal);
        __syncthreads();

        int off = 0, total = 0;
#pragma unroll
        for (int w = 0; w < 16; ++w) {
            int c = s_cnt[w];
            if (w < warp) off += c;
            total += c;
        }
        if (s > 0.5f) {
            int r = off + __popc(bal & ((1u << lane) - 1u));
            s_list[r] = (short)p;
        }
        if (p == 0) s_total = total;
        __syncthreads();

        // ---- gather phase: threads 0..127, float4 per thread ----
        if (p < 128) {
            const int col = p;     // float4 column index (covers cols 4p..4p+3)
            float4 a0 = make_float4(0.f, 0.f, 0.f, 0.f);
            float4 a1 = a0, a2 = a0, a3 = a0;

            const int nchunks = total >> 3;     // full chunks of 8 rows
            float4 buf[2][8];

            if (nchunks > 0) {
#pragma unroll
                for (int u = 0; u < 8; ++u)
                    buf[0][u] = __ldg(&RT4[(int)s_list[u] * 128 + col]);
            }
            for (int c = 0; c < nchunks; ++c) {
                const int curb = c & 1;
                const int nxtb = curb ^ 1;
                if (c + 1 < nchunks) {
                    const int base = (c + 1) * 8;
#pragma unroll
                    for (int u = 0; u < 8; ++u)
                        buf[nxtb][u] = __ldg(&RT4[(int)s_list[base + u] * 128 + col]);
                }
                // positions c*8+u ; slot = u%4 (8 is a multiple of 4)
#pragma unroll
                for (int u = 0; u < 8; ++u) {
                    float4 rv = buf[curb][u];
                    if ((u & 3) == 0) { a0.x += rv.x; a0.y += rv.y; a0.z += rv.z; a0.w += rv.w; }
                    else if ((u & 3) == 1) { a1.x += rv.x; a1.y += rv.y; a1.z += rv.z; a1.w += rv.w; }
                    else if ((u & 3) == 2) { a2.x += rv.x; a2.y += rv.y; a2.z += rv.z; a2.w += rv.w; }
                    else { a3.x += rv.x; a3.y += rv.y; a3.z += rv.z; a3.w += rv.w; }
                }
            }
            int j = nchunks * 8;
            if (j + 4 <= total) {   // one more full group of 4 (R1 main loop)
                float4 r0 = __ldg(&RT4[(int)s_list[j + 0] * 128 + col]);
                float4 r1 = __ldg(&RT4[(int)s_list[j + 1] * 128 + col]);
                float4 r2 = __ldg(&RT4[(int)s_list[j + 2] * 128 + col]);
                float4 r3 = __ldg(&RT4[(int)s_list[j + 3] * 128 + col]);
                a0.x += r0.x; a0.y += r0.y; a0.z += r0.z; a0.w += r0.w;
                a1.x += r1.x; a1.y += r1.y; a1.z += r1.z; a1.w += r1.w;
                a2.x += r2.x; a2.y += r2.y; a2.z += r2.z; a2.w += r2.w;
                a3.x += r3.x; a3.y += r3.y; a3.z += r3.z; a3.w += r3.w;
                j += 4;
            }
            for (; j < total; ++j) {   // tail -> acc0 (verbatim R1 semantics)
                float4 rv = __ldg(&RT4[(int)s_list[j] * 128 + col]);
                a0.x += rv.x; a0.y += rv.y; a0.z += rv.z; a0.w += rv.w;
            }
            // rec partial = ((a0+a1)+(a2+a3)) per column, exactly R1's combine
            recbuf[4 * col + 0] = (a0.x + a1.x) + (a2.x + a3.x);
            recbuf[4 * col + 1] = (a0.y + a1.y) + (a2.y + a3.y);
            recbuf[4 * col + 2] = (a0.z + a1.z) + (a2.z + a3.z);
            recbuf[4 * col + 3] = (a0.w + a1.w) + (a2.w + a3.w);
        }
        __syncthreads();

        // ---- LIF state update (verbatim R1: rec = zv + gathered sum) ----
        float zv = g_z[((size_t)t * N_DIM + n) * CO + p];
        float rec = zv + recbuf[p];
        cur = 0.75f * cur + rec;
        v   = 0.9f * v * (1.f - s) + cur;
        float s_new = (v >= 1.0f) ? 1.f : 0.f;
        s = s_new;

        // ---- stage output at q = t+1; flush every 16 steps (verbatim R1) ----
        int q = t + 1;
        stage[p * STAGE_STRIDE + (q & (STAGE_T - 1))] = s_new;

        if ((q & (STAGE_T - 1)) == STAGE_T - 1) {
            __syncthreads();
            int qbase = q & ~(STAGE_T - 1);
#pragma unroll
            for (int it = 0; it < STAGE_T; ++it) {
                int vidx = it * 512 + p;
                int pp = vidx >> 4;
                int tt = vidx & (STAGE_T - 1);
                out[((size_t)n * CO + pp) * T_DIM + qbase + tt] =
                    stage[pp * STAGE_STRIDE + tt];
            }
        }
        __syncthreads();   // protects s_cnt / s_list / recbuf / stage reuse
    }
}

// ---------------------------------------------------------------------------
// Launch
// ---------------------------------------------------------------------------
extern "C" void kernel_launch(void* const* d_in, const int* in_sizes, int n_in,
                              void* d_out, int out_size)
{
    const float* x = (const float*)d_in[0];   // [32, 512, 1024]
    const float* W = (const float*)d_in[1];   // [512, 512]
    const float* R = (const float*)d_in[2];   // [512, 512]
    float* out = (float*)d_out;               // [32, 512, 1024]

    transpose_R_kernel<<<(CO * CO) / 256, 256>>>(R);

    dim3 ggrid(T_DIM / BM, CO / BN, N_DIM);
    gemm_z_kernel<<<ggrid, 256>>>(x, W);

    scan_kernel<<<N_DIM, 512>>>(out);
}

// round 5
// speedup vs baseline: 1.6950x; 1.3201x over previous
#include <cuda_runtime.h>
#include <cooperative_groups.h>
#include <cstdint>

namespace cg = cooperative_groups;

// Problem constants
#define T_DIM 1024
#define N_DIM 32
#define CI    512
#define CO    512

// Scan decomposition
#define CSIZE  4               // CTAs per cluster (one cluster per batch)
#define PSLICE 128             // neurons per CTA
#define ROWS_S 416             // RT rows cached in smem; rows >=416 from L2

// Scratch (allocation-free rule: __device__ globals)
__device__ float g_z[T_DIM * N_DIM * CO];   // [t][n][o]
__device__ float g_RT[CO * CO];             // RT[o][p] = R[p][o]

// ---------------------------------------------------------------------------
// Kernel 1: transpose R -> RT.
// ---------------------------------------------------------------------------
__global__ void transpose_R_kernel(const float* __restrict__ R) {
    int idx = blockIdx.x * blockDim.x + threadIdx.x;   // idx = o*CO + p
    int o = idx >> 9;
    int p = idx & 511;
    g_RT[idx] = R[p * CO + o];
}

// ---------------------------------------------------------------------------
// Kernel 2: z[t][n][o] = sum_c x[n][c][t] * W[o][c]   (proven R1/R4)
// ---------------------------------------------------------------------------
#define BM 128
#define BN 64
#define BK 16
#define WS_STRIDE 68

__global__ __launch_bounds__(256) void gemm_z_kernel(
    const float* __restrict__ x, const float* __restrict__ W)
{
    __shared__ float xs[BK][BM];
    __shared__ float ws[BK][WS_STRIDE];

    const int n  = blockIdx.z;
    const int t0 = blockIdx.x * BM;
    const int o0 = blockIdx.y * BN;
    const int tid = threadIdx.x;
    const int tx = tid & 15;
    const int ty = tid >> 4;

    float acc[8][4];
#pragma unroll
    for (int i = 0; i < 8; ++i)
#pragma unroll
        for (int j = 0; j < 4; ++j) acc[i][j] = 0.f;

    const float* xbase = x + (size_t)n * CI * T_DIM + t0;

    for (int c0 = 0; c0 < CI; c0 += BK) {
#pragma unroll
        for (int it = 0; it < 8; ++it) {
            int idx = tid + it * 256;
            int cc = idx >> 7;
            int tt = idx & 127;
            xs[cc][tt] = xbase[(c0 + cc) * T_DIM + tt];
        }
#pragma unroll
        for (int it = 0; it < 4; ++it) {
            int idx = tid + it * 256;
            int oo = idx >> 4;
            int cc = idx & 15;
            ws[cc][oo] = W[(o0 + oo) * CI + (c0 + cc)];
        }
        __syncthreads();

#pragma unroll
        for (int k = 0; k < BK; ++k) {
            float a[8], b[4];
#pragma unroll
            for (int i = 0; i < 8; ++i) a[i] = xs[k][ty * 8 + i];
#pragma unroll
            for (int j = 0; j < 4; ++j) b[j] = ws[k][tx * 4 + j];
#pragma unroll
            for (int i = 0; i < 8; ++i)
#pragma unroll
                for (int j = 0; j < 4; ++j)
                    acc[i][j] += a[i] * b[j];
        }
        __syncthreads();
    }

#pragma unroll
    for (int i = 0; i < 8; ++i) {
        int t = t0 + ty * 8 + i;
        float4 v4 = make_float4(acc[i][0], acc[i][1], acc[i][2], acc[i][3]);
        *(float4*)&g_z[((size_t)t * N_DIM + n) * CO + o0 + tx * 4] = v4;
    }
}

// ---------------------------------------------------------------------------
// Kernel 3: cluster-parallel LIF scan.
// One cluster (4 CTAs x 128 thr) per batch n. CTA rank owns neurons
// [rank*128, rank*128+128); RT rows [0,416) for those columns live in smem,
// rows [416,512) come from L2 (sorted list => they sit at the list tail).
// Accumulation order is BIT-IDENTICAL to the R1/R4 passing kernels:
// chunks of 8 (slot = pos mod 4), one group of 4, scalar tail -> a0,
// rec = zv + ((a0+a1)+(a2+a3)).
// ---------------------------------------------------------------------------
#define RTS_ELEMS   (ROWS_S * PSLICE)
#define STAGE_ELEMS (PSLICE * 17)
#define SMEM_BYTES  (RTS_ELEMS * 4 + STAGE_ELEMS * 4 + 16 * 4 + 4 + 512 * 2)

extern __shared__ float smem_dyn[];

__global__ void __cluster_dims__(CSIZE, 1, 1) __launch_bounds__(PSLICE, 1)
scan_kernel(float* __restrict__ out)
{
    float*    RTs     = smem_dyn;                              // [416][128]
    float*    stage   = RTs + RTS_ELEMS;                       // [128][17]
    unsigned* masks   = (unsigned*)(stage + STAGE_ELEMS);      // [16]
    int*      s_total = (int*)(masks + 16);
    short*    s_list  = (short*)(s_total + 1);                 // [512]

    cg::cluster_group cluster = cg::this_cluster();
    const int rank = (int)cluster.block_rank();
    const int n    = blockIdx.x / CSIZE;

    const int tid  = threadIdx.x;
    const int warp = tid >> 5;
    const int lane = tid & 31;
    const int p    = rank * PSLICE + tid;      // this thread's neuron

    // Load this CTA's RT slice into smem (coalesced).
#pragma unroll 4
    for (int o = 0; o < ROWS_S; ++o)
        RTs[o * PSLICE + tid] = g_RT[o * CO + p];

    float cur = 0.f, v = 0.f, s = 0.f;
    stage[tid * 17 + 0] = 0.f;   // delay-shift: out[...,0] = 0

    const float* RTs_col = RTs + tid;

    for (int t = 0; t < T_DIM - 1; ++t) {
        // prefetch z early; consumed only at the LIF update
        float zv = g_z[((size_t)t * N_DIM + n) * CO + p];

        // ---- broadcast this warp's spike mask word to all cluster CTAs ----
        unsigned bal = __ballot_sync(0xffffffffu, s > 0.5f);
        if (lane < CSIZE) {
            unsigned* dst = cluster.map_shared_rank(&masks[rank * 4 + warp],
                                                    (unsigned)lane);
            *dst = bal;
        }
        cluster.sync();   // all 16 mask words visible in every CTA

        // ---- warp 0 builds the single sorted spike list ----
        if (warp == 0) {
            unsigned w = 0; int cnt = 0;
            if (lane < 16) { w = masks[lane]; cnt = __popc(w); }
            int inc = cnt;
#pragma unroll
            for (int d = 1; d < 32; d <<= 1) {
                int u = __shfl_up_sync(0xffffffffu, inc, d);
                if (lane >= d) inc += u;
            }
            int exc = inc - cnt;
            int tot = __shfl_sync(0xffffffffu, inc, 15);
            if (lane < 16 && w) {
                int idx = exc;
                int base = lane * 32;
                unsigned m = w;
                while (m) { int b = __ffs(m) - 1; m &= m - 1;
                            s_list[idx++] = (short)(base + b); }
            }
            if (lane == 0) *s_total = tot;
        }
        __syncthreads();

        const int total = *s_total;

        // ---- gather: verbatim R4 loop; load source selected per row ----
        float a0 = 0.f, a1 = 0.f, a2 = 0.f, a3 = 0.f;

        const int nchunks = total >> 3;
        float buf[2][8];

        if (nchunks > 0) {
#pragma unroll
            for (int u = 0; u < 8; ++u) {
                int o = s_list[u];
                if (o < ROWS_S) buf[0][u] = RTs_col[o * PSLICE];
                else            buf[0][u] = __ldg(&g_RT[o * CO + p]);
            }
        }
        for (int c = 0; c < nchunks; ++c) {
            const int curb = c & 1;
            const int nxtb = curb ^ 1;
            if (c + 1 < nchunks) {
                const int base = (c + 1) * 8;
#pragma unroll
                for (int u = 0; u < 8; ++u) {
                    int o = s_list[base + u];
                    if (o < ROWS_S) buf[nxtb][u] = RTs_col[o * PSLICE];
                    else            buf[nxtb][u] = __ldg(&g_RT[o * CO + p]);
                }
            }
#pragma unroll
            for (int u = 0; u < 8; ++u) {
                float rv = buf[curb][u];
                if      ((u & 3) == 0) a0 += rv;
                else if ((u & 3) == 1) a1 += rv;
                else if ((u & 3) == 2) a2 += rv;
                else                   a3 += rv;
            }
        }
        int j = nchunks * 8;
        if (j + 4 <= total) {
            int o0 = s_list[j + 0], o1 = s_list[j + 1];
            int o2 = s_list[j + 2], o3 = s_list[j + 3];
            float r0 = (o0 < ROWS_S) ? RTs_col[o0 * PSLICE] : __ldg(&g_RT[o0 * CO + p]);
            float r1 = (o1 < ROWS_S) ? RTs_col[o1 * PSLICE] : __ldg(&g_RT[o1 * CO + p]);
            float r2 = (o2 < ROWS_S) ? RTs_col[o2 * PSLICE] : __ldg(&g_RT[o2 * CO + p]);
            float r3 = (o3 < ROWS_S) ? RTs_col[o3 * PSLICE] : __ldg(&g_RT[o3 * CO + p]);
            a0 += r0; a1 += r1; a2 += r2; a3 += r3;
            j += 4;
        }
        for (; j < total; ++j) {
            int o = s_list[j];
            float rv = (o < ROWS_S) ? RTs_col[o * PSLICE] : __ldg(&g_RT[o * CO + p]);
            a0 += rv;
        }

        // ---- LIF state update (identical combine to R1/R4) ----
        float rec = zv + ((a0 + a1) + (a2 + a3));
        cur = 0.75f * cur + rec;
        v   = 0.9f * v * (1.f - s) + cur;
        float s_new = (v >= 1.0f) ? 1.f : 0.f;
        s = s_new;

        // ---- stage output at q = t+1; flush every 16 steps, coalesced ----
        const int q = t + 1;
        stage[tid * 17 + (q & 15)] = s_new;

        if ((q & 15) == 15) {
            __syncthreads();
            const int qbase = q & ~15;
#pragma unroll
            for (int it = 0; it < 16; ++it) {
                int vidx = it * PSLICE + tid;
                int pp = vidx >> 4;
                int tt = vidx & 15;
                out[((size_t)n * CO + rank * PSLICE + pp) * T_DIM + qbase + tt] =
                    stage[pp * 17 + tt];
            }
        }

        // end-of-step guard: masks/list/stage must not be rewritten until
        // every thread in the cluster is done reading them.
        cluster.sync();
    }
}

// ---------------------------------------------------------------------------
// Launch
// ---------------------------------------------------------------------------
extern "C" void kernel_launch(void* const* d_in, const int* in_sizes, int n_in,
                              void* d_out, int out_size)
{
    const float* x = (const float*)d_in[0];   // [32, 512, 1024]
    const float* W = (const float*)d_in[1];   // [512, 512]
    const float* R = (const float*)d_in[2];   // [512, 512]
    float* out = (float*)d_out;               // [32, 512, 1024]

    cudaFuncSetAttribute(scan_kernel,
                         cudaFuncAttributeMaxDynamicSharedMemorySize,
                         SMEM_BYTES);

    transpose_R_kernel<<<(CO * CO) / 256, 256>>>(R);

    dim3 ggrid(T_DIM / BM, CO / BN, N_DIM);
    gemm_z_kernel<<<ggrid, 256>>>(x, W);

    scan_kernel<<<N_DIM * CSIZE, PSLICE, SMEM_BYTES>>>(out);
}

// round 6
// speedup vs baseline: 2.4110x; 1.4224x over previous
#include <cuda_runtime.h>
#include <cooperative_groups.h>
#include <cstdint>

namespace cg = cooperative_groups;

// Problem constants
#define T_DIM 1024
#define N_DIM 32
#define CI    512
#define CO    512

// Scan decomposition
#define CSIZE  4               // CTAs per cluster (one cluster per batch)
#define PSLICE 128             // neurons per CTA
#define ROWS_S 416             // RT rows cached in smem; rows >=416 from L2
#define NTHR   512             // 4 slot-groups x 128 neuron columns

// Scratch (allocation-free rule: __device__ globals)
__device__ float g_z[T_DIM * N_DIM * CO];   // [t][n][o]
__device__ float g_RT[CO * CO];             // RT[o][p] = R[p][o]

// ---------------------------------------------------------------------------
// Kernel 1: transpose R -> RT.
// ---------------------------------------------------------------------------
__global__ void transpose_R_kernel(const float* __restrict__ R) {
    int idx = blockIdx.x * blockDim.x + threadIdx.x;   // idx = o*CO + p
    int o = idx >> 9;
    int p = idx & 511;
    g_RT[idx] = R[p * CO + o];
}

// ---------------------------------------------------------------------------
// Kernel 2: z[t][n][o] = sum_c x[n][c][t] * W[o][c]   (proven R1/R4/R5)
// ---------------------------------------------------------------------------
#define BM 128
#define BN 64
#define BK 16
#define WS_STRIDE 68

__global__ __launch_bounds__(256) void gemm_z_kernel(
    const float* __restrict__ x, const float* __restrict__ W)
{
    __shared__ float xs[BK][BM];
    __shared__ float ws[BK][WS_STRIDE];

    const int n  = blockIdx.z;
    const int t0 = blockIdx.x * BM;
    const int o0 = blockIdx.y * BN;
    const int tid = threadIdx.x;
    const int tx = tid & 15;
    const int ty = tid >> 4;

    float acc[8][4];
#pragma unroll
    for (int i = 0; i < 8; ++i)
#pragma unroll
        for (int j = 0; j < 4; ++j) acc[i][j] = 0.f;

    const float* xbase = x + (size_t)n * CI * T_DIM + t0;

    for (int c0 = 0; c0 < CI; c0 += BK) {
#pragma unroll
        for (int it = 0; it < 8; ++it) {
            int idx = tid + it * 256;
            int cc = idx >> 7;
            int tt = idx & 127;
            xs[cc][tt] = xbase[(c0 + cc) * T_DIM + tt];
        }
#pragma unroll
        for (int it = 0; it < 4; ++it) {
            int idx = tid + it * 256;
            int oo = idx >> 4;
            int cc = idx & 15;
            ws[cc][oo] = W[(o0 + oo) * CI + (c0 + cc)];
        }
        __syncthreads();

#pragma unroll
        for (int k = 0; k < BK; ++k) {
            float a[8], b[4];
#pragma unroll
            for (int i = 0; i < 8; ++i) a[i] = xs[k][ty * 8 + i];
#pragma unroll
            for (int j = 0; j < 4; ++j) b[j] = ws[k][tx * 4 + j];
#pragma unroll
            for (int i = 0; i < 8; ++i)
#pragma unroll
                for (int j = 0; j < 4; ++j)
                    acc[i][j] += a[i] * b[j];
        }
        __syncthreads();
    }

#pragma unroll
    for (int i = 0; i < 8; ++i) {
        int t = t0 + ty * 8 + i;
        float4 v4 = make_float4(acc[i][0], acc[i][1], acc[i][2], acc[i][3]);
        *(float4*)&g_z[((size_t)t * N_DIM + n) * CO + o0 + tx * 4] = v4;
    }
}

// ---------------------------------------------------------------------------
// Kernel 3: cluster-parallel LIF scan, slot-parallel gather (512 thr/CTA).
// Accumulation order bit-identical to R1/R4/R5:
//   slot(pos) = pos mod 4 for pos in [0, total&~3), tail -> a0;
//   rec = zv + ((a0+a1)+(a2+a3)).
// Thread = slot*128 + col. Slot k sums its positions in order; combine via
// smem. One cluster.sync per step (parity double-buffered masks).
// smem RT layout: row 0 = zero sentinel, rows 1..416 = RT rows 0..415.
// ---------------------------------------------------------------------------
#define RTS_ROWS    (ROWS_S + 1)                 // + zero sentinel at row 0
#define RTS_ELEMS   (RTS_ROWS * PSLICE)
#define STAGE_ELEMS (PSLICE * 17)
#define SMEM_BYTES  (RTS_ELEMS * 4 + STAGE_ELEMS * 4 + 3 * PSLICE * 4 \
                     + 2 * 16 * 4 + 4 + 512 * 2)

extern __shared__ float smem_dyn[];

__device__ __forceinline__ float load_row(int idx, int cnt, int slot,
                                          const short* s_list,
                                          const float* RTc,
                                          const float* gcol)
{
    int o = (idx < cnt) ? (int)s_list[slot + (idx << 2)] : -1;  // -1 -> zero row
    return (o < ROWS_S) ? RTc[(o + 1) * PSLICE] : __ldg(&gcol[o * CO]);
}

__global__ void __cluster_dims__(CSIZE, 1, 1) __launch_bounds__(NTHR, 1)
scan_kernel(float* __restrict__ out)
{
    float*    RTs     = smem_dyn;                              // [417][128]
    float*    stage   = RTs + RTS_ELEMS;                       // [128][17]
    float*    comb    = stage + STAGE_ELEMS;                   // [3][128]
    unsigned* masks   = (unsigned*)(comb + 3 * PSLICE);        // [2][16]
    int*      s_total = (int*)(masks + 32);
    short*    s_list  = (short*)(s_total + 1);                 // [512]

    cg::cluster_group cluster = cg::this_cluster();
    const int rank = (int)cluster.block_rank();
    const int n    = blockIdx.x / CSIZE;

    const int tid  = threadIdx.x;
    const int warp = tid >> 5;
    const int lane = tid & 31;
    const int slot = tid >> 7;          // 0..3 accumulator slot
    const int col  = tid & 127;         // neuron column within slice
    const int p    = rank * PSLICE + col;   // global neuron (column in g_RT)

    // Load RT slice: smem row 0 = zeros, rows 1..416 = g_RT rows 0..415.
    for (int o = tid; o < RTS_ROWS * 4; o += NTHR) {
        // o enumerates (row, quarter-of-row): 4 chunks of 32 cols per row
        int row = o >> 2;
        int c4  = (o & 3) * 32;
        // covered below by simpler per-row loop instead
    }
    // simpler: each thread strides rows for its own column
    {
        RTs[0 * PSLICE + col] = 0.f;                      // all 4 slots write same value
        for (int o = slot; o < ROWS_S; o += 4)
            RTs[(o + 1) * PSLICE + col] = g_RT[o * CO + p];
    }

    float cur = 0.f, v = 0.f, s = 0.f;
    if (slot == 0) stage[col * 17 + 0] = 0.f;   // delay-shift: out[...,0] = 0

    const float* RTc  = RTs + col;
    const float* gcol = g_RT + p;

    __syncthreads();   // RTs ready (cluster.sync below also orders rank-local)

    for (int t = 0; t < T_DIM - 1; ++t) {
        const int par = t & 1;
        float zv = 0.f;

        if (slot == 0) {
            // prefetch z early; consumed only at the LIF update
            zv = g_z[((size_t)t * N_DIM + n) * CO + p];

            // broadcast this warp's spike mask word to all cluster CTAs
            unsigned bal = __ballot_sync(0xffffffffu, s > 0.5f);
            if (lane < CSIZE) {
                unsigned* dst = cluster.map_shared_rank(
                    &masks[par * 16 + rank * 4 + warp], (unsigned)lane);
                *dst = bal;
            }
        }
        cluster.sync();   // masks[par] visible everywhere; also full CTA barrier

        // ---- warp 0 builds the single sorted spike list ----
        if (warp == 0) {
            unsigned w = 0; int cnt = 0;
            if (lane < 16) { w = masks[par * 16 + lane]; cnt = __popc(w); }
            int inc = cnt;
#pragma unroll
            for (int d = 1; d < 32; d <<= 1) {
                int u = __shfl_up_sync(0xffffffffu, inc, d);
                if (lane >= d) inc += u;
            }
            int exc = inc - cnt;
            int tot = __shfl_sync(0xffffffffu, inc, 15);
            if (lane < 16 && w) {
                int idx = exc;
                int base = lane * 32;
                unsigned m = w;
                while (m) { int b = __ffs(m) - 1; m &= m - 1;
                            s_list[idx++] = (short)(base + b); }
            }
            if (lane == 0) *s_total = tot;
        }
        __syncthreads();

        const int total = *s_total;
        const int M4    = total & ~3;
        const int cnt   = (M4 > slot) ? ((M4 - slot + 3) >> 2) : 0;
        const int nblk  = (cnt + 7) >> 3;

        // ---- slot gather: software-pipelined, spill-free double buffer ----
        float acc = 0.f;
        if (nblk > 0) {
            float bufA[8], bufB[8];
#pragma unroll
            for (int u = 0; u < 8; ++u)
                bufA[u] = load_row(u, cnt, slot, s_list, RTc, gcol);

            for (int b = 0; b < nblk; b += 2) {
                const int baseB = (b + 1) * 8;
#pragma unroll
                for (int u = 0; u < 8; ++u)
                    bufB[u] = load_row(baseB + u, cnt, slot, s_list, RTc, gcol);
#pragma unroll
                for (int u = 0; u < 8; ++u) acc += bufA[u];

                const int baseA = (b + 2) * 8;
#pragma unroll
                for (int u = 0; u < 8; ++u)
                    bufA[u] = load_row(baseA + u, cnt, slot, s_list, RTc, gcol);
                if (b + 1 < nblk) {
#pragma unroll
                    for (int u = 0; u < 8; ++u) acc += bufB[u];
                }
            }
        }
        // slot 0 adds the <4 tail rows (positions M4..total-1), in order
        if (slot == 0 && M4 < total) {
            int rem = total - M4;   // 1..3
            int o0 = s_list[M4];
            float r0 = (o0 < ROWS_S) ? RTc[(o0 + 1) * PSLICE] : __ldg(&gcol[o0 * CO]);
            float r1 = 0.f, r2 = 0.f;
            if (rem > 1) { int o1 = s_list[M4 + 1];
                r1 = (o1 < ROWS_S) ? RTc[(o1 + 1) * PSLICE] : __ldg(&gcol[o1 * CO]); }
            if (rem > 2) { int o2 = s_list[M4 + 2];
                r2 = (o2 < ROWS_S) ? RTc[(o2 + 1) * PSLICE] : __ldg(&gcol[o2 * CO]); }
            acc += r0; acc += r1; acc += r2;   // +0.0f is bit-exact identity
        }

        // ---- combine slots ----
        if (slot != 0) comb[(slot - 1) * PSLICE + col] = acc;
        __syncthreads();

        if (slot == 0) {
            float a1 = comb[col];
            float a2 = comb[PSLICE + col];
            float a3 = comb[2 * PSLICE + col];
            float rec = zv + ((acc + a1) + (a2 + a3));

            cur = 0.75f * cur + rec;
            v   = 0.9f * v * (1.f - s) + cur;
            float s_new = (v >= 1.0f) ? 1.f : 0.f;
            s = s_new;

            stage[col * 17 + ((t + 1) & 15)] = s_new;
        }

        // ---- flush stage every 16 steps, coalesced, all 512 threads ----
        if (((t + 1) & 15) == 15) {
            __syncthreads();
            const int qbase = (t + 1) & ~15;
#pragma unroll
            for (int it = 0; it < 4; ++it) {
                int vidx = it * NTHR + tid;
                int pp = vidx >> 4;
                int tt = vidx & 15;
                out[((size_t)n * CO + rank * PSLICE + pp) * T_DIM + qbase + tt] =
                    stage[pp * 17 + tt];
            }
        }
        // next iteration's cluster.sync orders all shared-buffer reuse
    }
}

// ---------------------------------------------------------------------------
// Launch
// ---------------------------------------------------------------------------
extern "C" void kernel_launch(void* const* d_in, const int* in_sizes, int n_in,
                              void* d_out, int out_size)
{
    const float* x = (const float*)d_in[0];   // [32, 512, 1024]
    const float* W = (const float*)d_in[1];   // [512, 512]
    const float* R = (const float*)d_in[2];   // [512, 512]
    float* out = (float*)d_out;               // [32, 512, 1024]

    cudaFuncSetAttribute(scan_kernel,
                         cudaFuncAttributeMaxDynamicSharedMemorySize,
                         SMEM_BYTES);

    transpose_R_kernel<<<(CO * CO) / 256, 256>>>(R);

    dim3 ggrid(T_DIM / BM, CO / BN, N_DIM);
    gemm_z_kernel<<<ggrid, 256>>>(x, W);

    scan_kernel<<<N_DIM * CSIZE, NTHR, SMEM_BYTES>>>(out);
}

// round 7
// speedup vs baseline: 4.6322x; 1.9213x over previous
#include <cuda_runtime.h>
#include <cooperative_groups.h>
#include <cstdint>

namespace cg = cooperative_groups;

// Problem constants
#define T_DIM 1024
#define N_DIM 32
#define CI    512
#define CO    512

// Scan decomposition
#define CSIZE  4               // CTAs per cluster (one cluster per batch)
#define PSLICE 128             // neurons per CTA
#define ROWS_S 416             // RT rows cached in smem; rows >=416 from L2
#define NTHR   512             // 4 slot-groups x 128 neuron columns

// Scratch (allocation-free rule: __device__ globals)
__device__ float g_z[T_DIM * N_DIM * CO];   // [t][n][o]
__device__ float g_RT[CO * CO];             // RT[o][p] = R[p][o]

// ---------------------------------------------------------------------------
// Kernel 1: transpose R -> RT.
// ---------------------------------------------------------------------------
__global__ void transpose_R_kernel(const float* __restrict__ R) {
    int idx = blockIdx.x * blockDim.x + threadIdx.x;   // idx = o*CO + p
    int o = idx >> 9;
    int p = idx & 511;
    g_RT[idx] = R[p * CO + o];
}

// ---------------------------------------------------------------------------
// Kernel 2: z GEMM — FROZEN since R1 (numerics proven; do not reorder).
// ---------------------------------------------------------------------------
#define BM 128
#define BN 64
#define BK 16
#define WS_STRIDE 68

__global__ __launch_bounds__(256) void gemm_z_kernel(
    const float* __restrict__ x, const float* __restrict__ W)
{
    __shared__ float xs[BK][BM];
    __shared__ float ws[BK][WS_STRIDE];

    const int n  = blockIdx.z;
    const int t0 = blockIdx.x * BM;
    const int o0 = blockIdx.y * BN;
    const int tid = threadIdx.x;
    const int tx = tid & 15;
    const int ty = tid >> 4;

    float acc[8][4];
#pragma unroll
    for (int i = 0; i < 8; ++i)
#pragma unroll
        for (int j = 0; j < 4; ++j) acc[i][j] = 0.f;

    const float* xbase = x + (size_t)n * CI * T_DIM + t0;

    for (int c0 = 0; c0 < CI; c0 += BK) {
#pragma unroll
        for (int it = 0; it < 8; ++it) {
            int idx = tid + it * 256;
            int cc = idx >> 7;
            int tt = idx & 127;
            xs[cc][tt] = xbase[(c0 + cc) * T_DIM + tt];
        }
#pragma unroll
        for (int it = 0; it < 4; ++it) {
            int idx = tid + it * 256;
            int oo = idx >> 4;
            int cc = idx & 15;
            ws[cc][oo] = W[(o0 + oo) * CI + (c0 + cc)];
        }
        __syncthreads();

#pragma unroll
        for (int k = 0; k < BK; ++k) {
            float a[8], b[4];
#pragma unroll
            for (int i = 0; i < 8; ++i) a[i] = xs[k][ty * 8 + i];
#pragma unroll
            for (int j = 0; j < 4; ++j) b[j] = ws[k][tx * 4 + j];
#pragma unroll
            for (int i = 0; i < 8; ++i)
#pragma unroll
                for (int j = 0; j < 4; ++j)
                    acc[i][j] += a[i] * b[j];
        }
        __syncthreads();
    }

#pragma unroll
    for (int i = 0; i < 8; ++i) {
        int t = t0 + ty * 8 + i;
        float4 v4 = make_float4(acc[i][0], acc[i][1], acc[i][2], acc[i][3]);
        *(float4*)&g_z[((size_t)t * N_DIM + n) * CO + o0 + tx * 4] = v4;
    }
}

// ---------------------------------------------------------------------------
// Kernel 3: cluster-parallel LIF scan, slot-parallel gather.
// Bit-exact accumulation order (R1/R4/R5/R6): slot(pos)=pos mod 4 for
// pos < (total & ~3); tail -> a0; rec = zv + ((a0+a1)+(a2+a3)).
// This round: parallel list build into 4 padded slot lists, int4 list loads,
// tail-blocks-first LDG scheduling.
// smem RT layout: row 0 = zero sentinel, rows 1..416 = RT rows 0..415.
// ---------------------------------------------------------------------------
#define RTS_ROWS    (ROWS_S + 1)
#define RTS_ELEMS   (RTS_ROWS * PSLICE)
#define STAGE_ELEMS (PSLICE * 17)
// layout: RTs | stage | comb[3*128] | masks[2*16] | lists[4*128 shorts] | tail[8 shorts]
#define SMEM_BYTES  (RTS_ELEMS * 4 + STAGE_ELEMS * 4 + 3 * PSLICE * 4 \
                     + 32 * 4 + 4 * 128 * 2 + 8 * 2)

extern __shared__ float smem_dyn[];

// Load 8 rows of this thread's column, given 8 packed int16 indices.
// Index -1 (padding sentinel) maps to the smem zero row.
__device__ __forceinline__ void load8(const int4* __restrict__ l4, int b,
                                      const float* __restrict__ RTc,
                                      const float* __restrict__ gcol,
                                      float dst[8])
{
    int4 w = l4[b];
    int o;
    o = (int)(short)(w.x & 0xffff);
    dst[0] = (o < ROWS_S) ? RTc[(o + 1) * PSLICE] : __ldg(&gcol[o * CO]);
    o = (int)(short)(w.x >> 16);
    dst[1] = (o < ROWS_S) ? RTc[(o + 1) * PSLICE] : __ldg(&gcol[o * CO]);
    o = (int)(short)(w.y & 0xffff);
    dst[2] = (o < ROWS_S) ? RTc[(o + 1) * PSLICE] : __ldg(&gcol[o * CO]);
    o = (int)(short)(w.y >> 16);
    dst[3] = (o < ROWS_S) ? RTc[(o + 1) * PSLICE] : __ldg(&gcol[o * CO]);
    o = (int)(short)(w.z & 0xffff);
    dst[4] = (o < ROWS_S) ? RTc[(o + 1) * PSLICE] : __ldg(&gcol[o * CO]);
    o = (int)(short)(w.z >> 16);
    dst[5] = (o < ROWS_S) ? RTc[(o + 1) * PSLICE] : __ldg(&gcol[o * CO]);
    o = (int)(short)(w.w & 0xffff);
    dst[6] = (o < ROWS_S) ? RTc[(o + 1) * PSLICE] : __ldg(&gcol[o * CO]);
    o = (int)(short)(w.w >> 16);
    dst[7] = (o < ROWS_S) ? RTc[(o + 1) * PSLICE] : __ldg(&gcol[o * CO]);
}

__global__ void __cluster_dims__(CSIZE, 1, 1) __launch_bounds__(NTHR, 1)
scan_kernel(float* __restrict__ out)
{
    float*    RTs   = smem_dyn;                              // [417][128]
    float*    stage = RTs + RTS_ELEMS;                       // [128][17]
    float*    comb  = stage + STAGE_ELEMS;                   // [3][128]
    unsigned* masks = (unsigned*)(comb + 3 * PSLICE);        // [2][16]
    short*    lists = (short*)(masks + 32);                  // [4][128]
    short*    tail  = lists + 4 * 128;                       // [8]

    cg::cluster_group cluster = cg::this_cluster();
    const int rank = (int)cluster.block_rank();
    const int n    = blockIdx.x / CSIZE;

    const int tid  = threadIdx.x;
    const int warp = tid >> 5;
    const int lane = tid & 31;
    const int slot = tid >> 7;              // 0..3 accumulator slot
    const int col  = tid & 127;             // neuron column within slice
    const int p    = rank * PSLICE + col;   // global neuron (column in g_RT)

    // RT slice: smem row 0 = zeros, rows 1..416 = g_RT rows 0..415.
    RTs[col] = 0.f;   // all 4 slots write the same zeros -> harmless
    for (int o = slot; o < ROWS_S; o += 4)
        RTs[(o + 1) * PSLICE + col] = g_RT[o * CO + p];

    float cur = 0.f, v = 0.f, s = 0.f;
    if (slot == 0) stage[col * 17 + 0] = 0.f;   // delay shift: out[...,0]=0

    const float* RTc  = RTs + col;
    const float* gcol = g_RT + p;
    const int4*  l4   = (const int4*)(lists + slot * 128);

    __syncthreads();

    for (int t = 0; t < T_DIM - 1; ++t) {
        const int par = t & 1;
        float zv = 0.f;

        if (slot == 0) {
            zv = g_z[((size_t)t * N_DIM + n) * CO + p];   // hidden under sync
            unsigned bal = __ballot_sync(0xffffffffu, s > 0.5f);
            if (lane < CSIZE) {
                unsigned* dst = cluster.map_shared_rank(
                    &masks[par * 16 + rank * 4 + warp], (unsigned)lane);
                *dst = bal;
            }
        }
        cluster.sync();   // masks[par] visible everywhere; full cluster barrier

        // ---- parallel list build: thread tid handles candidate o = tid ----
        const unsigned* mw = masks + par * 16;
        unsigned myw = mw[warp];                          // broadcast LDS
        int cw = (lane < 16) ? __popc(mw[lane]) : 0;      // word popcounts
        int inc = cw;
#pragma unroll
        for (int d = 1; d < 16; d <<= 1) {
            int u = __shfl_up_sync(0xffffffffu, inc, d);
            if (lane >= d) inc += u;
        }
        const int tot   = __shfl_sync(0xffffffffu, inc, 15);
        const int exc_w = (warp == 0) ? 0
                          : __shfl_sync(0xffffffffu, inc, warp - 1);
        const int M4 = tot & ~3;

        if ((myw >> lane) & 1u) {
            int rk = exc_w + __popc(myw & ((1u << lane) - 1u));
            if (rk < M4) lists[(rk & 3) * 128 + (rk >> 2)] = (short)tid;
            else         tail[rk - M4] = (short)tid;
        }
        const int cnt     = M4 >> 2;            // identical for all slots
        const int cnt_pad = (cnt + 7) & ~7;
        if (tid < 32) {                          // pad with zero-row sentinel
            int k = tid >> 3, j = tid & 7;
            if (cnt + j < cnt_pad) lists[k * 128 + cnt + j] = (short)(-1);
        }
        __syncthreads();

        const int nblk = cnt_pad >> 3;

        // ---- slot gather: tail blocks first (their LDGs get max latency
        //      cover), then pipelined smem blocks; adds in exact block order.
        float acc = 0.f;
        if (nblk >= 3) {
            float T[16];
            load8(l4, nblk - 2, RTc, gcol, T);
            load8(l4, nblk - 1, RTc, gcol, T + 8);

            float A[8], B[8];
            load8(l4, 0, RTc, gcol, A);
            const int nb = nblk - 2;             // blocks 0..nb-1
            for (int b = 0; b < nb; b += 2) {
                if (b + 1 < nb) load8(l4, b + 1, RTc, gcol, B);
#pragma unroll
                for (int u = 0; u < 8; ++u) acc += A[u];
                if (b + 2 < nb) load8(l4, b + 2, RTc, gcol, A);
                if (b + 1 < nb) {
#pragma unroll
                    for (int u = 0; u < 8; ++u) acc += B[u];
                }
            }
#pragma unroll
            for (int u = 0; u < 16; ++u) acc += T[u];
        } else if (nblk > 0) {
            float T[8];
            for (int b = 0; b < nblk; ++b) {
                load8(l4, b, RTc, gcol, T);
#pragma unroll
                for (int u = 0; u < 8; ++u) acc += T[u];
            }
        }
        // slot 0 adds the <4 tail rows (positions M4..tot-1), in order
        if (slot == 0 && M4 < tot) {
            int rem = tot - M4;
            int o0 = tail[0];
            float r0 = (o0 < ROWS_S) ? RTc[(o0 + 1) * PSLICE] : __ldg(&gcol[o0 * CO]);
            float r1 = 0.f, r2 = 0.f;
            if (rem > 1) { int o1 = tail[1];
                r1 = (o1 < ROWS_S) ? RTc[(o1 + 1) * PSLICE] : __ldg(&gcol[o1 * CO]); }
            if (rem > 2) { int o2 = tail[2];
                r2 = (o2 < ROWS_S) ? RTc[(o2 + 1) * PSLICE] : __ldg(&gcol[o2 * CO]); }
            acc += r0; acc += r1; acc += r2;     // +0.0f is bit-exact identity
        }

        // ---- combine slots (rec = zv + ((a0+a1)+(a2+a3))) ----
        if (slot != 0) comb[(slot - 1) * PSLICE + col] = acc;
        __syncthreads();

        if (slot == 0) {
            float a1 = comb[col];
            float a2 = comb[PSLICE + col];
            float a3 = comb[2 * PSLICE + col];
            float rec = zv + ((acc + a1) + (a2 + a3));

            cur = 0.75f * cur + rec;
            v   = 0.9f * v * (1.f - s) + cur;
            float s_new = (v >= 1.0f) ? 1.f : 0.f;
            s = s_new;

            stage[col * 17 + ((t + 1) & 15)] = s_new;
        }

        // ---- flush stage every 16 steps, coalesced, all 512 threads ----
        if (((t + 1) & 15) == 15) {
            __syncthreads();
            const int qbase = (t + 1) & ~15;
#pragma unroll
            for (int it = 0; it < 4; ++it) {
                int vidx = it * NTHR + tid;
                int pp = vidx >> 4;
                int tt = vidx & 15;
                out[((size_t)n * CO + rank * PSLICE + pp) * T_DIM + qbase + tt] =
                    stage[pp * 17 + tt];
            }
        }
        // next iteration's cluster.sync orders all shared-buffer reuse
    }
}

// ---------------------------------------------------------------------------
// Launch
// ---------------------------------------------------------------------------
extern "C" void kernel_launch(void* const* d_in, const int* in_sizes, int n_in,
                              void* d_out, int out_size)
{
    const float* x = (const float*)d_in[0];   // [32, 512, 1024]
    const float* W = (const float*)d_in[1];   // [512, 512]
    const float* R = (const float*)d_in[2];   // [512, 512]
    float* out = (float*)d_out;               // [32, 512, 1024]

    cudaFuncSetAttribute(scan_kernel,
                         cudaFuncAttributeMaxDynamicSharedMemorySize,
                         SMEM_BYTES);

    transpose_R_kernel<<<(CO * CO) / 256, 256>>>(R);

    dim3 ggrid(T_DIM / BM, CO / BN, N_DIM);
    gemm_z_kernel<<<ggrid, 256>>>(x, W);

    scan_kernel<<<N_DIM * CSIZE, NTHR, SMEM_BYTES>>>(out);
}